// round 10
// baseline (speedup 1.0000x reference)
#include <cuda_runtime.h>
#include <cuda_bf16.h>
#include <math.h>
#include <cstdint>

#define BB 16
#define TT 8192
#define DD 512
#define AA 512
#define EPSF 1e-8f

// k_energy smem layout (per CTA, dynamic)
#define LDB_B 528u         // B row stride bytes (256 n bf16 + 16B pad): 4-bank row shift
#define A_OFF 0u           // 64 rows x 1024B, XOR-swizzled = 65536
#define B_OFF 65536u       // 2 bufs x (32 rows x 528B) = 33792
#define BUF_B 16896u       // one B buffer bytes
#define BI_OFF 99328u      // 4 x 512 f32 = 8192
#define EB_OFF 107520u     // 64 f32
#define SMEM_E 107776u

__device__ __forceinline__ float tanh_fast(float x){
    float y; asm("tanh.approx.f32 %0, %1;" : "=f"(y) : "f"(x)); return y;
}
__device__ __forceinline__ uint32_t smem_u32(const void* p){
    uint32_t a;
    asm("{ .reg .u64 t; cvta.to.shared.u64 t, %1; cvt.u32.u64 %0, t; }" : "=r"(a) : "l"(p));
    return a;
}
__device__ __forceinline__ void cp_async16(uint32_t dst, const void* src){
    asm volatile("cp.async.cg.shared.global [%0], [%1], 16;" :: "r"(dst), "l"(src));
}
__device__ __forceinline__ void cp_commit(){ asm volatile("cp.async.commit_group;"); }
__device__ __forceinline__ void cp_wait1(){ asm volatile("cp.async.wait_group 1;"); }

__device__ __forceinline__ void ldmx4(uint32_t* r, uint32_t addr){
    asm volatile("ldmatrix.sync.aligned.m8n8.x4.shared.b16 {%0,%1,%2,%3}, [%4];"
        : "=r"(r[0]),"=r"(r[1]),"=r"(r[2]),"=r"(r[3]) : "r"(addr));
}
__device__ __forceinline__ void ldmx4t(uint32_t* r, uint32_t addr){
    asm volatile("ldmatrix.sync.aligned.m8n8.x4.trans.shared.b16 {%0,%1,%2,%3}, [%4];"
        : "=r"(r[0]),"=r"(r[1]),"=r"(r[2]),"=r"(r[3]) : "r"(addr));
}
__device__ __forceinline__ void mma16816(float* c, const uint32_t* a, const uint32_t* b){
    asm volatile("mma.sync.aligned.m16n8k16.row.col.f32.bf16.bf16.f32 "
        "{%0,%1,%2,%3}, {%4,%5,%6,%7}, {%8,%9}, {%0,%1,%2,%3};"
        : "+f"(c[0]),"+f"(c[1]),"+f"(c[2]),"+f"(c[3])
        : "r"(a[0]),"r"(a[1]),"r"(a[2]),"r"(a[3]), "r"(b[0]),"r"(b[1]));
}

// ---------------- device scratch ----------------
__device__ __align__(256) float g_bias_m[BB*AA];
__device__ __align__(256) float g_bias_c[BB*AA];
__device__ __align__(256) float g_wv[2*AA];
__device__ __align__(256) float g_add[2];
__device__ __align__(256) __nv_bfloat16 g_wkm[DD*AA];   // row-major [k][n]
__device__ __align__(256) __nv_bfloat16 g_wkc[DD*AA];
__device__ __align__(256) float g_em[BB*TT];
__device__ __align__(256) float g_ec[BB*TT];
__device__ __align__(256) float g_se[BB*TT];

// ---------------- prep: v_w scale + scalar biases ----------------
__global__ void k_prep(const float* __restrict__ m_vv, const float* __restrict__ m_vg,
                       const float* __restrict__ m_vb, const float* __restrict__ m_r,
                       const float* __restrict__ c_vv, const float* __restrict__ c_vg,
                       const float* __restrict__ c_vb, const float* __restrict__ c_r){
    __shared__ float red[512];
    int tid = threadIdx.x;
    float v = m_vv[tid];
    red[tid] = v*v;
    __syncthreads();
    for (int s=256; s>0; s>>=1){ if (tid<s) red[tid]+=red[tid+s]; __syncthreads(); }
    float scale_m = m_vg[0] / sqrtf(red[0]);
    __syncthreads();
    g_wv[tid] = v * scale_m;

    float vc = c_vv[tid];
    red[tid] = vc*vc;
    __syncthreads();
    for (int s=256; s>0; s>>=1){ if (tid<s) red[tid]+=red[tid+s]; __syncthreads(); }
    float scale_c = c_vg[0] / sqrtf(red[0]);
    g_wv[AA+tid] = vc * scale_c;
    if (tid==0){ g_add[0]=m_vb[0]+m_r[0]; g_add[1]=c_vb[0]+c_r[0]; }
}

// ---------------- bias: q@wq + bk ----------------
__global__ void k_bias(const float* __restrict__ query,
                       const float* __restrict__ m_wq, const float* __restrict__ m_bk,
                       const float* __restrict__ c_wq, const float* __restrict__ c_bk){
    __shared__ float q[DD];
    int b = blockIdx.x, which = blockIdx.y, tid = threadIdx.x;
    q[tid] = query[b*DD + tid];
    __syncthreads();
    const float* wq = which ? c_wq : m_wq;
    const float* bk = which ? c_bk : m_bk;
    float s = 0.f;
    #pragma unroll 8
    for (int d=0; d<DD; d++) s += q[d] * wq[d*AA + tid];
    float* dst = which ? g_bias_c : g_bias_m;
    dst[b*AA + tid] = s + bk[tid];
}

// ---------------- convert weights fp32 -> bf16 (row-major) ----------------
__global__ void k_convw(const float* __restrict__ m_wk, const float* __restrict__ c_wk){
    int i = blockIdx.x*blockDim.x + threadIdx.x;
    if (i < DD*AA){
        g_wkm[i] = __float2bfloat16(m_wk[i]);
        g_wkc[i] = __float2bfloat16(c_wk[i]);
    }
}

// ---------------- energy: PTX mma GEMM, M=64/CTA, 4 warps, warp tile 64x64 ----
// Each warp owns ALL 64 M-rows and a private 64-n strip (no B re-reads).
// grid (TT/64, BB), 128 threads. 2 CTAs/SM.
__global__ __launch_bounds__(128, 2)
void k_energy(const float* __restrict__ key){
    extern __shared__ char smem[];
    float* bias_s = (float*)(smem + BI_OFF);
    float* eb     = (float*)(smem + EB_OFF);
    uint32_t sb = smem_u32(smem);

    int tid = threadIdx.x, wid = tid >> 5, lane = tid & 31;
    int b = blockIdx.y, t0 = blockIdx.x * 64;

    // bias / wv into smem
    for (int i = tid; i < 512; i += 128){
        bias_s[i]        = g_bias_m[b*AA + i];
        bias_s[512 + i]  = g_bias_c[b*AA + i];
        bias_s[1024 + i] = g_wv[i];
        bias_s[1536 + i] = g_wv[AA + i];
    }

    // A fill: 64 rows x 512 fp32 -> bf16, XOR-swizzled 16B units:
    // addr = m*1024 + ((u ^ (m&7))<<4), u = 16B-unit index 0..63
    {
        const float4* kv = (const float4*)(key + ((size_t)b*TT + t0)*DD);
        #pragma unroll 8
        for (int it = 0; it < 32; it++){
            int j = tid + 128*it;           // 0..4095 units
            int m = j >> 6;                 // row 0..63
            int u = j & 63;                 // unit
            float4 v0 = kv[m*(DD/4) + u*2];
            float4 v1 = kv[m*(DD/4) + u*2 + 1];
            __nv_bfloat162 p0 = __floats2bfloat162_rn(v0.x, v0.y);
            __nv_bfloat162 p1 = __floats2bfloat162_rn(v0.z, v0.w);
            __nv_bfloat162 p2 = __floats2bfloat162_rn(v1.x, v1.y);
            __nv_bfloat162 p3 = __floats2bfloat162_rn(v1.z, v1.w);
            uint4 val = make_uint4(*(uint32_t*)&p0, *(uint32_t*)&p1,
                                   *(uint32_t*)&p2, *(uint32_t*)&p3);
            *(uint4*)(smem + A_OFF + (uint32_t)m*1024u + (uint32_t)((u ^ (m&7))<<4)) = val;
        }
    }
    __syncthreads();

    // lane-level address components
    uint32_t lx7 = (uint32_t)(lane & 7);
    uint32_t aRow = sb + A_OFF + (uint32_t)(lane & 15)*1024u;  // + mi*16384 + swizzled col
    uint32_t aUb  = (uint32_t)(lane >> 4);                      // + kc*4 + ks*2
    uint32_t bLane = sb + B_OFF + (uint32_t)(lane & 15)*LDB_B
                   + (uint32_t)(wid*128) + (uint32_t)((lane >> 4)*16);

    float acc[4][8][4];

    for (int pass = 0; pass < 2; pass++){
        const __nv_bfloat16* W = pass ? g_wkc : g_wkm;
        if (tid < 64) eb[tid] = 0.f;
        __syncthreads();

        for (int nt = 0; nt < 2; nt++){
            // prefetch chunk 0 (32 k-rows x 256 n = 512B/row) into buffer 0
            #pragma unroll
            for (int it = 0; it < 8; it++){
                int j = tid + 128*it;            // 0..1023
                int row = j >> 5, u = j & 31;
                uint32_t dst = sb + B_OFF + (uint32_t)row*LDB_B + u*16;
                const char* src = (const char*)W + (size_t)row*(AA*2) + nt*512 + u*16;
                cp_async16(dst, src);
            }
            cp_commit();

            #pragma unroll
            for (int mi = 0; mi < 4; mi++)
                #pragma unroll
                for (int j = 0; j < 8; j++)
                    #pragma unroll
                    for (int c = 0; c < 4; c++) acc[mi][j][c] = 0.f;

            for (int kc = 0; kc < 16; kc++){
                int buf = kc & 1;
                if (kc < 15){
                    int nb = (kc + 1) & 1;
                    #pragma unroll
                    for (int it = 0; it < 8; it++){
                        int j = tid + 128*it;
                        int row = j >> 5, u = j & 31;
                        uint32_t dst = sb + B_OFF + (uint32_t)nb*BUF_B + (uint32_t)row*LDB_B + u*16;
                        const char* src = (const char*)W + (size_t)((kc+1)*32 + row)*(AA*2)
                                          + nt*512 + u*16;
                        cp_async16(dst, src);
                    }
                }
                cp_commit();
                cp_wait1();
                __syncthreads();

                uint32_t bB = bLane + (uint32_t)buf*BUF_B;
                #pragma unroll
                for (int ks = 0; ks < 2; ks++){
                    // A fragments: 4 x ldmx4, rows mi*16..+16, k = kc*32 + ks*16
                    uint32_t u = aUb + (uint32_t)kc*4u + (uint32_t)ks*2u;
                    uint32_t su = (u ^ lx7) << 4;
                    uint32_t a[4][4];
                    #pragma unroll
                    for (int mi = 0; mi < 4; mi++)
                        ldmx4(a[mi], aRow + (uint32_t)mi*16384u + su);
                    uint32_t bks = bB + (uint32_t)ks*16u*LDB_B;
                    #pragma unroll
                    for (int nq = 0; nq < 4; nq++){
                        uint32_t br[4];
                        ldmx4t(br, bks + nq*32u);
                        #pragma unroll
                        for (int mi = 0; mi < 4; mi++){
                            mma16816(acc[mi][nq*2],     a[mi], &br[0]);
                            mma16816(acc[mi][nq*2 + 1], a[mi], &br[2]);
                        }
                    }
                }
                __syncthreads();
            }

            // direct-fragment epilogue: tanh(acc + bias) * wv over this warp's 64-n strip
            {
                const float2* bias2 = (const float2*)(bias_s + pass*512);
                const float2* wv2   = (const float2*)(bias_s + 1024 + pass*512);
                int cq = (nt*256 + wid*64 + (lane&3)*2) >> 1;   // float2 index
                #pragma unroll
                for (int mi = 0; mi < 4; mi++){
                    float slo = 0.f, shi = 0.f;
                    #pragma unroll
                    for (int j = 0; j < 8; j++){
                        float2 bw = bias2[cq + j*4];
                        float2 wv = wv2[cq + j*4];
                        slo += tanh_fast(acc[mi][j][0] + bw.x)*wv.x
                             + tanh_fast(acc[mi][j][1] + bw.y)*wv.y;
                        shi += tanh_fast(acc[mi][j][2] + bw.x)*wv.x
                             + tanh_fast(acc[mi][j][3] + bw.y)*wv.y;
                    }
                    slo += __shfl_xor_sync(0xffffffffu, slo, 1);
                    slo += __shfl_xor_sync(0xffffffffu, slo, 2);
                    shi += __shfl_xor_sync(0xffffffffu, shi, 1);
                    shi += __shfl_xor_sync(0xffffffffu, shi, 2);
                    if ((lane & 3) == 0){
                        int row = mi*16 + (lane >> 2);
                        atomicAdd(&eb[row],     slo);
                        atomicAdd(&eb[row + 8], shi);
                    }
                }
            }
        }
        __syncthreads();
        float* out = pass ? g_ec : g_em;
        if (tid < 64) out[b*TT + t0 + tid] = eb[tid] + g_add[pass];
        __syncthreads();
    }
}

// ---------------- block inclusive scan ----------------
__device__ __forceinline__ float blockScan(float v, float* ws, int tid){
    __syncthreads();
    int lane = tid & 31, wid = tid >> 5;
    float x = v;
    #pragma unroll
    for (int o=1;o<32;o<<=1){ float y=__shfl_up_sync(0xffffffffu, x, o); if (lane>=o) x+=y; }
    if (lane==31) ws[wid]=x;
    __syncthreads();
    if (wid==0){
        float w = ws[lane];
        #pragma unroll
        for (int o=1;o<32;o<<=1){ float y=__shfl_up_sync(0xffffffffu, w, o); if (lane>=o) w+=y; }
        ws[lane]=w;
    }
    __syncthreads();
    float off = wid ? ws[wid-1] : 0.f;
    return x + off;
}

__global__ void k_scan(const float* __restrict__ noise, const float* __restrict__ aw_prev,
                       float* __restrict__ alpha_out){
    __shared__ float ws[32];
    __shared__ float redm[32];
    __shared__ float sh_max;
    int b = blockIdx.x, tid = threadIdx.x, lane = tid&31, wid = tid>>5;
    const float* em = g_em + b*TT;
    const float* ec = g_ec + b*TT;
    const float* nz = noise + b*TT;
    const float* aw = aw_prev + b*TT;
    float* ao = alpha_out + b*TT;
    float* seo = g_se + b*TT;

    float m = -3.4e38f;
    for (int t=tid; t<TT; t+=1024) m = fmaxf(m, ec[t]);
    #pragma unroll
    for (int o=16;o>0;o>>=1) m = fmaxf(m, __shfl_xor_sync(0xffffffffu, m, o));
    if (lane==0) redm[wid] = m;
    __syncthreads();
    if (wid==0){
        float mm = redm[lane];
        #pragma unroll
        for (int o=16;o>0;o>>=1) mm = fmaxf(mm, __shfl_xor_sync(0xffffffffu, mm, o));
        if (lane==0) sh_max = mm;
    }
    __syncthreads();
    float cmax = sh_max;

    float carry_l = 0.f, carry_r = 0.f;
    for (int tile=0; tile<TT/1024; tile++){
        int t = tile*1024 + tid;
        float e = em[t];
        float p = 1.f / (1.f + expf(-(e + nz[t])));
        float omp = fminf(fmaxf(1.f - p, EPSF), 1.f);
        float l = logf(omp);
        float Ls = blockScan(l, ws, tid);
        float total_l = ws[31];
        float cumprod = expf(carry_l + Ls - l);
        float cp_c = fminf(fmaxf(cumprod, EPSF), 1.f);
        float ratio = aw[t] / cp_c;
        float Rs = blockScan(ratio, ws, tid);
        float total_r = ws[31];
        float S2 = carry_r + Rs;
        ao[t] = p * cumprod * S2;
        seo[t] = fmaxf(expf(ec[t] - cmax), 1e-5f);
        carry_l += total_l;
        carry_r += total_r;
    }
}

// ---------------- beta ----------------
__global__ void k_beta(const float* __restrict__ alpha, float* __restrict__ beta){
    int b = blockIdx.y;
    int t = blockIdx.x*256 + threadIdx.x;
    const float* se = g_se + b*TT;
    float sum = 0.f;
    #pragma unroll
    for (int j=0;j<4;j++){
        int tj = t + j;
        if (tj < TT){
            float d = 0.f;
            #pragma unroll
            for (int i=0;i<4;i++){
                int ti = tj - i;
                if (ti >= 0) d += se[ti];
            }
            sum += alpha[b*TT + tj] / d;
        }
    }
    beta[b*TT + t] = se[t] * sum;
}

// ---------------- cv = beta . value ----------------
__global__ void k_initcv(float* out){
    int i = blockIdx.x*blockDim.x + threadIdx.x;
    if (i < BB*DD) out[i] = 0.f;
}

__global__ void k_cv(const float* __restrict__ value, const float* __restrict__ beta,
                     float* __restrict__ cv){
    int b = blockIdx.y;
    int s = blockIdx.x;
    int tid = threadIdx.x;
    int t0 = s * (TT/64);
    float4 acc = make_float4(0.f,0.f,0.f,0.f);
    const float4* val = (const float4*)(value + (size_t)b*TT*DD);
    for (int t=0; t<TT/64; t++){
        float bv = beta[b*TT + t0 + t];
        float4 v = val[(size_t)(t0+t)*(DD/4) + tid];
        acc.x += bv*v.x; acc.y += bv*v.y; acc.z += bv*v.z; acc.w += bv*v.w;
    }
    float* dst = cv + b*DD + tid*4;
    atomicAdd(dst+0, acc.x); atomicAdd(dst+1, acc.y);
    atomicAdd(dst+2, acc.z); atomicAdd(dst+3, acc.w);
}

// ---------------- launch ----------------
extern "C" void kernel_launch(void* const* d_in, const int* in_sizes, int n_in,
                              void* d_out, int out_size){
    const float* key   = (const float*)d_in[0];
    const float* value = (const float*)d_in[1];
    const float* query = (const float*)d_in[2];
    const float* noise = (const float*)d_in[3];
    const float* aw    = (const float*)d_in[4];
    // d_in[5] = mask, all-true by construction, ignored
    const float* m_wk = (const float*)d_in[6];
    const float* m_bk = (const float*)d_in[7];
    const float* m_wq = (const float*)d_in[8];
    const float* m_vv = (const float*)d_in[9];
    const float* m_vg = (const float*)d_in[10];
    const float* m_vb = (const float*)d_in[11];
    const float* m_r  = (const float*)d_in[12];
    const float* c_wk = (const float*)d_in[13];
    const float* c_bk = (const float*)d_in[14];
    const float* c_wq = (const float*)d_in[15];
    const float* c_vv = (const float*)d_in[16];
    const float* c_vg = (const float*)d_in[17];
    const float* c_vb = (const float*)d_in[18];
    const float* c_r  = (const float*)d_in[19];

    float* out   = (float*)d_out;
    float* cv    = out;                     // B*D
    float* alpha = out + BB*DD;             // B*T
    float* beta  = out + BB*DD + BB*TT;     // B*T

    cudaFuncSetAttribute(k_energy, cudaFuncAttributeMaxDynamicSharedMemorySize, SMEM_E);

    k_prep<<<1,512>>>(m_vv,m_vg,m_vb,m_r,c_vv,c_vg,c_vb,c_r);
    k_bias<<<dim3(BB,2),512>>>(query,m_wq,m_bk,c_wq,c_bk);
    k_convw<<<(DD*AA+255)/256,256>>>(m_wk,c_wk);
    k_energy<<<dim3(TT/64,BB),128,SMEM_E>>>(key);
    k_scan<<<BB,1024>>>(noise,aw,alpha);
    k_initcv<<<(BB*DD+1023)/1024,1024>>>(cv);
    k_beta<<<dim3(TT/256,BB),256>>>(alpha,beta);
    k_cv<<<dim3(64,BB),128>>>(value,beta,cv);
}

// round 11
// speedup vs baseline: 1.3944x; 1.3944x over previous
#include <cuda_runtime.h>
#include <cuda_bf16.h>
#include <math.h>
#include <cstdint>

#define BB 16
#define TT 8192
#define DD 512
#define AA 512
#define EPSF 1e-8f

// k_energy smem layout (per CTA, dynamic)
#define LDA_B 1040u        // A row stride bytes (520 bf16): 4-bank row shift, ldmatrix conflict-free
#define LDB_B 528u         // B row stride bytes (264 bf16): 4-bank row shift
#define A_OFF 0u           // 64 rows x 1040B = 66560
#define B_OFF 66560u       // 2 bufs x (32 rows x 528B) = 33792
#define BUF_B 16896u       // one B buffer bytes
#define BI_OFF 100352u     // 4 x 512 f32 = 8192
#define EB_OFF 108544u     // 64 f32
#define SMEM_E 108800u

__device__ __forceinline__ float tanh_fast(float x){
    float y; asm("tanh.approx.f32 %0, %1;" : "=f"(y) : "f"(x)); return y;
}
__device__ __forceinline__ uint32_t smem_u32(const void* p){
    uint32_t a;
    asm("{ .reg .u64 t; cvta.to.shared.u64 t, %1; cvt.u32.u64 %0, t; }" : "=r"(a) : "l"(p));
    return a;
}
__device__ __forceinline__ void cp_async16(uint32_t dst, const void* src){
    asm volatile("cp.async.cg.shared.global [%0], [%1], 16;" :: "r"(dst), "l"(src));
}
__device__ __forceinline__ void cp_commit(){ asm volatile("cp.async.commit_group;"); }
__device__ __forceinline__ void cp_wait1(){ asm volatile("cp.async.wait_group 1;"); }

__device__ __forceinline__ void ldmx4(uint32_t* r, uint32_t addr){
    asm volatile("ldmatrix.sync.aligned.m8n8.x4.shared.b16 {%0,%1,%2,%3}, [%4];"
        : "=r"(r[0]),"=r"(r[1]),"=r"(r[2]),"=r"(r[3]) : "r"(addr));
}
__device__ __forceinline__ void ldmx4t(uint32_t* r, uint32_t addr){
    asm volatile("ldmatrix.sync.aligned.m8n8.x4.trans.shared.b16 {%0,%1,%2,%3}, [%4];"
        : "=r"(r[0]),"=r"(r[1]),"=r"(r[2]),"=r"(r[3]) : "r"(addr));
}
__device__ __forceinline__ void mma16816(float* c, const uint32_t* a, const uint32_t* b){
    asm volatile("mma.sync.aligned.m16n8k16.row.col.f32.bf16.bf16.f32 "
        "{%0,%1,%2,%3}, {%4,%5,%6,%7}, {%8,%9}, {%0,%1,%2,%3};"
        : "+f"(c[0]),"+f"(c[1]),"+f"(c[2]),"+f"(c[3])
        : "r"(a[0]),"r"(a[1]),"r"(a[2]),"r"(a[3]), "r"(b[0]),"r"(b[1]));
}

// ---------------- device scratch ----------------
__device__ __align__(256) float g_bias_m[BB*AA];
__device__ __align__(256) float g_bias_c[BB*AA];
__device__ __align__(256) float g_wv[2*AA];
__device__ __align__(256) float g_add[2];
__device__ __align__(256) __nv_bfloat16 g_wkm[DD*AA];   // row-major [k][n]
__device__ __align__(256) __nv_bfloat16 g_wkc[DD*AA];
__device__ __align__(256) float g_em[BB*TT];
__device__ __align__(256) float g_ec[BB*TT];
__device__ __align__(256) float g_se[BB*TT];

// ---------------- prep: v_w scale + scalar biases ----------------
__global__ void k_prep(const float* __restrict__ m_vv, const float* __restrict__ m_vg,
                       const float* __restrict__ m_vb, const float* __restrict__ m_r,
                       const float* __restrict__ c_vv, const float* __restrict__ c_vg,
                       const float* __restrict__ c_vb, const float* __restrict__ c_r){
    __shared__ float red[512];
    int tid = threadIdx.x;
    float v = m_vv[tid];
    red[tid] = v*v;
    __syncthreads();
    for (int s=256; s>0; s>>=1){ if (tid<s) red[tid]+=red[tid+s]; __syncthreads(); }
    float scale_m = m_vg[0] / sqrtf(red[0]);
    __syncthreads();
    g_wv[tid] = v * scale_m;

    float vc = c_vv[tid];
    red[tid] = vc*vc;
    __syncthreads();
    for (int s=256; s>0; s>>=1){ if (tid<s) red[tid]+=red[tid+s]; __syncthreads(); }
    float scale_c = c_vg[0] / sqrtf(red[0]);
    g_wv[AA+tid] = vc * scale_c;
    if (tid==0){ g_add[0]=m_vb[0]+m_r[0]; g_add[1]=c_vb[0]+c_r[0]; }
}

// ---------------- bias: q@wq + bk ----------------
__global__ void k_bias(const float* __restrict__ query,
                       const float* __restrict__ m_wq, const float* __restrict__ m_bk,
                       const float* __restrict__ c_wq, const float* __restrict__ c_bk){
    __shared__ float q[DD];
    int b = blockIdx.x, which = blockIdx.y, tid = threadIdx.x;
    q[tid] = query[b*DD + tid];
    __syncthreads();
    const float* wq = which ? c_wq : m_wq;
    const float* bk = which ? c_bk : m_bk;
    float s = 0.f;
    #pragma unroll 8
    for (int d=0; d<DD; d++) s += q[d] * wq[d*AA + tid];
    float* dst = which ? g_bias_c : g_bias_m;
    dst[b*AA + tid] = s + bk[tid];
}

// ---------------- convert weights fp32 -> bf16 (row-major) ----------------
__global__ void k_convw(const float* __restrict__ m_wk, const float* __restrict__ c_wk){
    int i = blockIdx.x*blockDim.x + threadIdx.x;
    if (i < DD*AA){
        g_wkm[i] = __float2bfloat16(m_wk[i]);
        g_wkc[i] = __float2bfloat16(c_wk[i]);
    }
}

// ---------------- energy: PTX mma GEMM, M=64/CTA, 8 warps (2x4), tile 32x64 ----
// grid (TT/64, BB), 256 threads. 2 CTAs/SM -> 4 warps/SMSP.
__global__ __launch_bounds__(256, 2)
void k_energy(const float* __restrict__ key){
    extern __shared__ char smem[];
    float* bias_s = (float*)(smem + BI_OFF);
    float* eb     = (float*)(smem + EB_OFF);
    uint32_t sb = smem_u32(smem);

    int tid = threadIdx.x, wid = tid >> 5, lane = tid & 31;
    int warp_m = wid >> 2, warp_n = wid & 3;     // 2 x 4 warp grid
    int b = blockIdx.y, t0 = blockIdx.x * 64;

    // bias / wv into smem
    for (int i = tid; i < 512; i += 256){
        bias_s[i]        = g_bias_m[b*AA + i];
        bias_s[512 + i]  = g_bias_c[b*AA + i];
        bias_s[1024 + i] = g_wv[i];
        bias_s[1536 + i] = g_wv[AA + i];
    }

    // A fill: 64 rows x 512 fp32 -> bf16 smem (stride 1040B)
    {
        const float4* kv = (const float4*)(key + ((size_t)b*TT + t0)*DD);
        #pragma unroll 8
        for (int it = 0; it < 32; it++){
            int j = tid + 256*it;           // 0..8191
            int m = j >> 7;                 // row 0..63
            int c4 = j & 127;
            float4 v = kv[m*(DD/4) + c4];
            __nv_bfloat162 lo = __floats2bfloat162_rn(v.x, v.y);
            __nv_bfloat162 hi = __floats2bfloat162_rn(v.z, v.w);
            uint2 val = make_uint2(*(uint32_t*)&lo, *(uint32_t*)&hi);
            *(uint2*)(smem + A_OFF + (uint32_t)m*LDA_B + c4*8) = val;
        }
    }
    __syncthreads();

    // lane-level ldmatrix base addresses
    uint32_t aBase = sb + A_OFF + (uint32_t)(warp_m*32 + (lane & 15))*LDA_B + (uint32_t)(lane >> 4)*16u;
    uint32_t bBase = sb + B_OFF + (uint32_t)(lane & 15)*LDB_B + (uint32_t)(warp_n*64 + (lane >> 4)*8)*2u;

    float acc[2][8][4];

    for (int pass = 0; pass < 2; pass++){
        const __nv_bfloat16* W = pass ? g_wkc : g_wkm;
        if (tid < 64) eb[tid] = 0.f;
        __syncthreads();

        for (int nt = 0; nt < 2; nt++){
            // prefetch kc=0 into buffer 0 (32 k-rows x 256 n = 512B/row)
            #pragma unroll
            for (int it = 0; it < 4; it++){
                int j = tid + 256*it;            // 0..1023
                int row = j >> 5, u = j & 31;
                uint32_t dst = sb + B_OFF + (uint32_t)row*LDB_B + u*16;
                const char* src = (const char*)W + (size_t)row*(AA*2) + nt*512 + u*16;
                cp_async16(dst, src);
            }
            cp_commit();

            #pragma unroll
            for (int mi = 0; mi < 2; mi++)
                #pragma unroll
                for (int j = 0; j < 8; j++)
                    #pragma unroll
                    for (int c = 0; c < 4; c++) acc[mi][j][c] = 0.f;

            for (int kc = 0; kc < 16; kc++){
                int buf = kc & 1;
                if (kc < 15){
                    int nb = (kc + 1) & 1;
                    #pragma unroll
                    for (int it = 0; it < 4; it++){
                        int j = tid + 256*it;
                        int row = j >> 5, u = j & 31;
                        uint32_t dst = sb + B_OFF + (uint32_t)nb*BUF_B + (uint32_t)row*LDB_B + u*16;
                        const char* src = (const char*)W + (size_t)((kc+1)*32 + row)*(AA*2)
                                          + nt*512 + u*16;
                        cp_async16(dst, src);
                    }
                }
                cp_commit();
                cp_wait1();
                __syncthreads();

                uint32_t aA = aBase + (uint32_t)kc*64u;       // 32 k = 64 bytes
                uint32_t bB = bBase + (uint32_t)buf*BUF_B;
                #pragma unroll
                for (int ks = 0; ks < 2; ks++){
                    uint32_t a[2][4];
                    ldmx4(a[0], aA + ks*32u);
                    ldmx4(a[1], aA + 16u*LDA_B + ks*32u);
                    uint32_t br[4][4];
                    #pragma unroll
                    for (int nq = 0; nq < 4; nq++)
                        ldmx4t(br[nq], bB + (uint32_t)ks*16u*LDB_B + nq*32u);
                    #pragma unroll
                    for (int mi = 0; mi < 2; mi++)
                        #pragma unroll
                        for (int j = 0; j < 8; j++)
                            mma16816(acc[mi][j], a[mi], &br[j>>1][(j&1)*2]);
                }
                __syncthreads();
            }

            // direct-fragment epilogue: tanh(acc + bias) * wv over this warp's 64-n strip
            {
                const float2* bias2 = (const float2*)(bias_s + pass*512);
                const float2* wv2   = (const float2*)(bias_s + 1024 + pass*512);
                int cq = (nt*256 + warp_n*64 + (lane&3)*2) >> 1;   // float2 index
                #pragma unroll
                for (int mi = 0; mi < 2; mi++){
                    float slo = 0.f, shi = 0.f;
                    #pragma unroll
                    for (int j = 0; j < 8; j++){
                        float2 bw = bias2[cq + j*4];
                        float2 wv = wv2[cq + j*4];
                        slo += tanh_fast(acc[mi][j][0] + bw.x)*wv.x
                             + tanh_fast(acc[mi][j][1] + bw.y)*wv.y;
                        shi += tanh_fast(acc[mi][j][2] + bw.x)*wv.x
                             + tanh_fast(acc[mi][j][3] + bw.y)*wv.y;
                    }
                    slo += __shfl_xor_sync(0xffffffffu, slo, 1);
                    slo += __shfl_xor_sync(0xffffffffu, slo, 2);
                    shi += __shfl_xor_sync(0xffffffffu, shi, 1);
                    shi += __shfl_xor_sync(0xffffffffu, shi, 2);
                    if ((lane & 3) == 0){
                        int row = warp_m*32 + mi*16 + (lane >> 2);
                        atomicAdd(&eb[row],     slo);
                        atomicAdd(&eb[row + 8], shi);
                    }
                }
            }
        }
        __syncthreads();
        float* out = pass ? g_ec : g_em;
        if (tid < 64) out[b*TT + t0 + tid] = eb[tid] + g_add[pass];
        __syncthreads();
    }
}

// ---------------- block inclusive scan ----------------
__device__ __forceinline__ float blockScan(float v, float* ws, int tid){
    __syncthreads();
    int lane = tid & 31, wid = tid >> 5;
    float x = v;
    #pragma unroll
    for (int o=1;o<32;o<<=1){ float y=__shfl_up_sync(0xffffffffu, x, o); if (lane>=o) x+=y; }
    if (lane==31) ws[wid]=x;
    __syncthreads();
    if (wid==0){
        float w = ws[lane];
        #pragma unroll
        for (int o=1;o<32;o<<=1){ float y=__shfl_up_sync(0xffffffffu, w, o); if (lane>=o) w+=y; }
        ws[lane]=w;
    }
    __syncthreads();
    float off = wid ? ws[wid-1] : 0.f;
    return x + off;
}

__global__ void k_scan(const float* __restrict__ noise, const float* __restrict__ aw_prev,
                       float* __restrict__ alpha_out){
    __shared__ float ws[32];
    __shared__ float redm[32];
    __shared__ float sh_max;
    int b = blockIdx.x, tid = threadIdx.x, lane = tid&31, wid = tid>>5;
    const float* em = g_em + b*TT;
    const float* ec = g_ec + b*TT;
    const float* nz = noise + b*TT;
    const float* aw = aw_prev + b*TT;
    float* ao = alpha_out + b*TT;
    float* seo = g_se + b*TT;

    float m = -3.4e38f;
    for (int t=tid; t<TT; t+=1024) m = fmaxf(m, ec[t]);
    #pragma unroll
    for (int o=16;o>0;o>>=1) m = fmaxf(m, __shfl_xor_sync(0xffffffffu, m, o));
    if (lane==0) redm[wid] = m;
    __syncthreads();
    if (wid==0){
        float mm = redm[lane];
        #pragma unroll
        for (int o=16;o>0;o>>=1) mm = fmaxf(mm, __shfl_xor_sync(0xffffffffu, mm, o));
        if (lane==0) sh_max = mm;
    }
    __syncthreads();
    float cmax = sh_max;

    float carry_l = 0.f, carry_r = 0.f;
    for (int tile=0; tile<TT/1024; tile++){
        int t = tile*1024 + tid;
        float e = em[t];
        float p = 1.f / (1.f + expf(-(e + nz[t])));
        float omp = fminf(fmaxf(1.f - p, EPSF), 1.f);
        float l = logf(omp);
        float Ls = blockScan(l, ws, tid);
        float total_l = ws[31];
        float cumprod = expf(carry_l + Ls - l);
        float cp_c = fminf(fmaxf(cumprod, EPSF), 1.f);
        float ratio = aw[t] / cp_c;
        float Rs = blockScan(ratio, ws, tid);
        float total_r = ws[31];
        float S2 = carry_r + Rs;
        ao[t] = p * cumprod * S2;
        seo[t] = fmaxf(expf(ec[t] - cmax), 1e-5f);
        carry_l += total_l;
        carry_r += total_r;
    }
}

// ---------------- beta ----------------
__global__ void k_beta(const float* __restrict__ alpha, float* __restrict__ beta){
    int b = blockIdx.y;
    int t = blockIdx.x*256 + threadIdx.x;
    const float* se = g_se + b*TT;
    float sum = 0.f;
    #pragma unroll
    for (int j=0;j<4;j++){
        int tj = t + j;
        if (tj < TT){
            float d = 0.f;
            #pragma unroll
            for (int i=0;i<4;i++){
                int ti = tj - i;
                if (ti >= 0) d += se[ti];
            }
            sum += alpha[b*TT + tj] / d;
        }
    }
    beta[b*TT + t] = se[t] * sum;
}

// ---------------- cv = beta . value ----------------
__global__ void k_initcv(float* out){
    int i = blockIdx.x*blockDim.x + threadIdx.x;
    if (i < BB*DD) out[i] = 0.f;
}

__global__ void k_cv(const float* __restrict__ value, const float* __restrict__ beta,
                     float* __restrict__ cv){
    int b = blockIdx.y;
    int s = blockIdx.x;
    int tid = threadIdx.x;
    int t0 = s * (TT/64);
    float4 acc = make_float4(0.f,0.f,0.f,0.f);
    const float4* val = (const float4*)(value + (size_t)b*TT*DD);
    for (int t=0; t<TT/64; t++){
        float bv = beta[b*TT + t0 + t];
        float4 v = val[(size_t)(t0+t)*(DD/4) + tid];
        acc.x += bv*v.x; acc.y += bv*v.y; acc.z += bv*v.z; acc.w += bv*v.w;
    }
    float* dst = cv + b*DD + tid*4;
    atomicAdd(dst+0, acc.x); atomicAdd(dst+1, acc.y);
    atomicAdd(dst+2, acc.z); atomicAdd(dst+3, acc.w);
}

// ---------------- launch ----------------
extern "C" void kernel_launch(void* const* d_in, const int* in_sizes, int n_in,
                              void* d_out, int out_size){
    const float* key   = (const float*)d_in[0];
    const float* value = (const float*)d_in[1];
    const float* query = (const float*)d_in[2];
    const float* noise = (const float*)d_in[3];
    const float* aw    = (const float*)d_in[4];
    // d_in[5] = mask, all-true by construction, ignored
    const float* m_wk = (const float*)d_in[6];
    const float* m_bk = (const float*)d_in[7];
    const float* m_wq = (const float*)d_in[8];
    const float* m_vv = (const float*)d_in[9];
    const float* m_vg = (const float*)d_in[10];
    const float* m_vb = (const float*)d_in[11];
    const float* m_r  = (const float*)d_in[12];
    const float* c_wk = (const float*)d_in[13];
    const float* c_bk = (const float*)d_in[14];
    const float* c_wq = (const float*)d_in[15];
    const float* c_vv = (const float*)d_in[16];
    const float* c_vg = (const float*)d_in[17];
    const float* c_vb = (const float*)d_in[18];
    const float* c_r  = (const float*)d_in[19];

    float* out   = (float*)d_out;
    float* cv    = out;                     // B*D
    float* alpha = out + BB*DD;             // B*T
    float* beta  = out + BB*DD + BB*TT;     // B*T

    cudaFuncSetAttribute(k_energy, cudaFuncAttributeMaxDynamicSharedMemorySize, SMEM_E);

    k_prep<<<1,512>>>(m_vv,m_vg,m_vb,m_r,c_vv,c_vg,c_vb,c_r);
    k_bias<<<dim3(BB,2),512>>>(query,m_wq,m_bk,c_wq,c_bk);
    k_convw<<<(DD*AA+255)/256,256>>>(m_wk,c_wk);
    k_energy<<<dim3(TT/64,BB),256,SMEM_E>>>(key);
    k_scan<<<BB,1024>>>(noise,aw,alpha);
    k_initcv<<<(BB*DD+1023)/1024,1024>>>(cv);
    k_beta<<<dim3(TT/256,BB),256>>>(alpha,beta);
    k_cv<<<dim3(64,BB),128>>>(value,beta,cv);
}

// round 12
// speedup vs baseline: 1.4263x; 1.0228x over previous
#include <cuda_runtime.h>
#include <cuda_bf16.h>
#include <math.h>
#include <cstdint>

#define BB 16
#define TT 8192
#define DD 512
#define AA 512
#define EPSF 1e-8f

// k_energy smem layout (per CTA, dynamic)
#define LDA_B 1040u        // A row stride bytes (520 bf16): 4-bank row shift, ldmatrix conflict-free
#define LDBW  144u         // warp-private B row stride bytes (64 n bf16 + 16B pad)
#define A_OFF 0u           // 64 rows x 1040B = 66560
#define BW_OFF 66560u      // 8 warps x 2 bufs x (16 rows x 144B) = 36864
#define BW_WARP 4608u      // per-warp B bytes (2 buffers)
#define BW_BUF  2304u      // one buffer
#define BI_OFF 103424u     // 4 x 512 f32 = 8192
#define EB_OFF 111616u     // 64 f32
#define SMEM_E 111872u

__device__ __forceinline__ float tanh_fast(float x){
    float y; asm("tanh.approx.f32 %0, %1;" : "=f"(y) : "f"(x)); return y;
}
__device__ __forceinline__ uint32_t smem_u32(const void* p){
    uint32_t a;
    asm("{ .reg .u64 t; cvta.to.shared.u64 t, %1; cvt.u32.u64 %0, t; }" : "=r"(a) : "l"(p));
    return a;
}
__device__ __forceinline__ void cp_async16(uint32_t dst, const void* src){
    asm volatile("cp.async.cg.shared.global [%0], [%1], 16;" :: "r"(dst), "l"(src));
}
__device__ __forceinline__ void cp_commit(){ asm volatile("cp.async.commit_group;"); }
__device__ __forceinline__ void cp_wait1(){ asm volatile("cp.async.wait_group 1;"); }

__device__ __forceinline__ void ldmx4(uint32_t* r, uint32_t addr){
    asm volatile("ldmatrix.sync.aligned.m8n8.x4.shared.b16 {%0,%1,%2,%3}, [%4];"
        : "=r"(r[0]),"=r"(r[1]),"=r"(r[2]),"=r"(r[3]) : "r"(addr));
}
__device__ __forceinline__ void ldmx4t(uint32_t* r, uint32_t addr){
    asm volatile("ldmatrix.sync.aligned.m8n8.x4.trans.shared.b16 {%0,%1,%2,%3}, [%4];"
        : "=r"(r[0]),"=r"(r[1]),"=r"(r[2]),"=r"(r[3]) : "r"(addr));
}
__device__ __forceinline__ void mma16816(float* c, const uint32_t* a, const uint32_t* b){
    asm volatile("mma.sync.aligned.m16n8k16.row.col.f32.bf16.bf16.f32 "
        "{%0,%1,%2,%3}, {%4,%5,%6,%7}, {%8,%9}, {%0,%1,%2,%3};"
        : "+f"(c[0]),"+f"(c[1]),"+f"(c[2]),"+f"(c[3])
        : "r"(a[0]),"r"(a[1]),"r"(a[2]),"r"(a[3]), "r"(b[0]),"r"(b[1]));
}

// ---------------- device scratch ----------------
__device__ __align__(256) float g_bias_m[BB*AA];
__device__ __align__(256) float g_bias_c[BB*AA];
__device__ __align__(256) float g_wv[2*AA];
__device__ __align__(256) float g_add[2];
__device__ __align__(256) __nv_bfloat16 g_wkm[DD*AA];   // row-major [k][n]
__device__ __align__(256) __nv_bfloat16 g_wkc[DD*AA];
__device__ __align__(256) float g_em[BB*TT];
__device__ __align__(256) float g_ec[BB*TT];
__device__ __align__(256) float g_se[BB*TT];

// ---------------- prep: v_w scale + scalar biases ----------------
__global__ void k_prep(const float* __restrict__ m_vv, const float* __restrict__ m_vg,
                       const float* __restrict__ m_vb, const float* __restrict__ m_r,
                       const float* __restrict__ c_vv, const float* __restrict__ c_vg,
                       const float* __restrict__ c_vb, const float* __restrict__ c_r){
    __shared__ float red[512];
    int tid = threadIdx.x;
    float v = m_vv[tid];
    red[tid] = v*v;
    __syncthreads();
    for (int s=256; s>0; s>>=1){ if (tid<s) red[tid]+=red[tid+s]; __syncthreads(); }
    float scale_m = m_vg[0] / sqrtf(red[0]);
    __syncthreads();
    g_wv[tid] = v * scale_m;

    float vc = c_vv[tid];
    red[tid] = vc*vc;
    __syncthreads();
    for (int s=256; s>0; s>>=1){ if (tid<s) red[tid]+=red[tid+s]; __syncthreads(); }
    float scale_c = c_vg[0] / sqrtf(red[0]);
    g_wv[AA+tid] = vc * scale_c;
    if (tid==0){ g_add[0]=m_vb[0]+m_r[0]; g_add[1]=c_vb[0]+c_r[0]; }
}

// ---------------- bias: q@wq + bk ----------------
__global__ void k_bias(const float* __restrict__ query,
                       const float* __restrict__ m_wq, const float* __restrict__ m_bk,
                       const float* __restrict__ c_wq, const float* __restrict__ c_bk){
    __shared__ float q[DD];
    int b = blockIdx.x, which = blockIdx.y, tid = threadIdx.x;
    q[tid] = query[b*DD + tid];
    __syncthreads();
    const float* wq = which ? c_wq : m_wq;
    const float* bk = which ? c_bk : m_bk;
    float s = 0.f;
    #pragma unroll 8
    for (int d=0; d<DD; d++) s += q[d] * wq[d*AA + tid];
    float* dst = which ? g_bias_c : g_bias_m;
    dst[b*AA + tid] = s + bk[tid];
}

// ---------------- convert weights fp32 -> bf16 (row-major) ----------------
__global__ void k_convw(const float* __restrict__ m_wk, const float* __restrict__ c_wk){
    int i = blockIdx.x*blockDim.x + threadIdx.x;
    if (i < DD*AA){
        g_wkm[i] = __float2bfloat16(m_wk[i]);
        g_wkc[i] = __float2bfloat16(c_wk[i]);
    }
}

// ---------------- energy: PTX mma GEMM, M=64/CTA, 8 warps (2x4), tile 32x64 ----
// Warp-private double-buffered B (cp.async group sync only) -> NO block barrier
// in the k-loop. grid (TT/64, BB), 256 threads, 2 CTAs/SM = 4 warps/SMSP.
__global__ __launch_bounds__(256, 2)
void k_energy(const float* __restrict__ key){
    extern __shared__ char smem[];
    float* bias_s = (float*)(smem + BI_OFF);
    float* eb     = (float*)(smem + EB_OFF);
    uint32_t sb = smem_u32(smem);

    int tid = threadIdx.x, wid = tid >> 5, lane = tid & 31;
    int warp_m = wid >> 2, warp_n = wid & 3;     // 2 x 4 warp grid
    int b = blockIdx.y, t0 = blockIdx.x * 64;

    // bias / wv into smem
    for (int i = tid; i < 512; i += 256){
        bias_s[i]        = g_bias_m[b*AA + i];
        bias_s[512 + i]  = g_bias_c[b*AA + i];
        bias_s[1024 + i] = g_wv[i];
        bias_s[1536 + i] = g_wv[AA + i];
    }

    // A fill: 64 rows x 512 fp32 -> bf16 smem (stride 1040B)
    {
        const float4* kv = (const float4*)(key + ((size_t)b*TT + t0)*DD);
        #pragma unroll 8
        for (int it = 0; it < 32; it++){
            int j = tid + 256*it;           // 0..8191
            int m = j >> 7;                 // row 0..63
            int c4 = j & 127;
            float4 v = kv[m*(DD/4) + c4];
            __nv_bfloat162 lo = __floats2bfloat162_rn(v.x, v.y);
            __nv_bfloat162 hi = __floats2bfloat162_rn(v.z, v.w);
            uint2 val = make_uint2(*(uint32_t*)&lo, *(uint32_t*)&hi);
            *(uint2*)(smem + A_OFF + (uint32_t)m*LDA_B + c4*8) = val;
        }
    }
    __syncthreads();

    // lane-level addresses
    uint32_t aBase = sb + A_OFF + (uint32_t)(warp_m*32 + (lane & 15))*LDA_B + (uint32_t)(lane >> 4)*16u;
    uint32_t bwBase = sb + BW_OFF + (uint32_t)wid*BW_WARP;
    uint32_t bLane  = bwBase + (uint32_t)(lane & 15)*LDBW + (uint32_t)(lane >> 4)*16u;
    int bRow = lane >> 3, bSeg = lane & 7;       // cp.async fill coords (4 iters of +4 rows)

    float acc[2][8][4];

    for (int pass = 0; pass < 2; pass++){
        const __nv_bfloat16* W = pass ? g_wkc : g_wkm;
        if (tid < 64) eb[tid] = 0.f;
        __syncthreads();

        for (int nt = 0; nt < 2; nt++){
            const char* Wbase = (const char*)W + (size_t)(nt*512 + warp_n*128);

            // prefetch chunk 0 into buffer 0 (16 k-rows x 64 n = 128B/row, warp-private)
            #pragma unroll
            for (int i = 0; i < 4; i++){
                int row = bRow + i*4;
                cp_async16(bwBase + (uint32_t)row*LDBW + bSeg*16,
                           Wbase + (size_t)row*(AA*2) + bSeg*16);
            }
            cp_commit();

            #pragma unroll
            for (int mi = 0; mi < 2; mi++)
                #pragma unroll
                for (int j = 0; j < 8; j++)
                    #pragma unroll
                    for (int c = 0; c < 4; c++) acc[mi][j][c] = 0.f;

            for (int kc = 0; kc < 32; kc++){
                if (kc < 31){
                    uint32_t nb = (uint32_t)((kc + 1) & 1);
                    const char* src = Wbase + (size_t)((kc+1)*16)*(AA*2);
                    #pragma unroll
                    for (int i = 0; i < 4; i++){
                        int row = bRow + i*4;
                        cp_async16(bwBase + nb*BW_BUF + (uint32_t)row*LDBW + bSeg*16,
                                   src + (size_t)row*(AA*2) + bSeg*16);
                    }
                }
                cp_commit();
                cp_wait1();

                uint32_t aA = aBase + (uint32_t)kc*32u;       // 16 k = 32 bytes
                uint32_t bB = bLane + (uint32_t)(kc & 1)*BW_BUF;
                uint32_t a[2][4];
                ldmx4(a[0], aA);
                ldmx4(a[1], aA + 16u*LDA_B);
                uint32_t br[4][4];
                #pragma unroll
                for (int nq = 0; nq < 4; nq++)
                    ldmx4t(br[nq], bB + nq*32u);
                #pragma unroll
                for (int mi = 0; mi < 2; mi++)
                    #pragma unroll
                    for (int j = 0; j < 8; j++)
                        mma16816(acc[mi][j], a[mi], &br[j>>1][(j&1)*2]);
            }

            // direct-fragment epilogue: tanh(acc + bias) * wv over this warp's 64-n strip
            {
                const float2* bias2 = (const float2*)(bias_s + pass*512);
                const float2* wv2   = (const float2*)(bias_s + 1024 + pass*512);
                int cq = (nt*256 + warp_n*64 + (lane&3)*2) >> 1;   // float2 index
                #pragma unroll
                for (int mi = 0; mi < 2; mi++){
                    float slo = 0.f, shi = 0.f;
                    #pragma unroll
                    for (int j = 0; j < 8; j++){
                        float2 bw = bias2[cq + j*4];
                        float2 wv = wv2[cq + j*4];
                        slo += tanh_fast(acc[mi][j][0] + bw.x)*wv.x
                             + tanh_fast(acc[mi][j][1] + bw.y)*wv.y;
                        shi += tanh_fast(acc[mi][j][2] + bw.x)*wv.x
                             + tanh_fast(acc[mi][j][3] + bw.y)*wv.y;
                    }
                    slo += __shfl_xor_sync(0xffffffffu, slo, 1);
                    slo += __shfl_xor_sync(0xffffffffu, slo, 2);
                    shi += __shfl_xor_sync(0xffffffffu, shi, 1);
                    shi += __shfl_xor_sync(0xffffffffu, shi, 2);
                    if ((lane & 3) == 0){
                        int row = warp_m*32 + mi*16 + (lane >> 2);
                        atomicAdd(&eb[row],     slo);
                        atomicAdd(&eb[row + 8], shi);
                    }
                }
            }
        }
        __syncthreads();
        float* out = pass ? g_ec : g_em;
        if (tid < 64) out[b*TT + t0 + tid] = eb[tid] + g_add[pass];
        __syncthreads();
    }
}

// ---------------- block inclusive scan ----------------
__device__ __forceinline__ float blockScan(float v, float* ws, int tid){
    __syncthreads();
    int lane = tid & 31, wid = tid >> 5;
    float x = v;
    #pragma unroll
    for (int o=1;o<32;o<<=1){ float y=__shfl_up_sync(0xffffffffu, x, o); if (lane>=o) x+=y; }
    if (lane==31) ws[wid]=x;
    __syncthreads();
    if (wid==0){
        float w = ws[lane];
        #pragma unroll
        for (int o=1;o<32;o<<=1){ float y=__shfl_up_sync(0xffffffffu, w, o); if (lane>=o) w+=y; }
        ws[lane]=w;
    }
    __syncthreads();
    float off = wid ? ws[wid-1] : 0.f;
    return x + off;
}

__global__ void k_scan(const float* __restrict__ noise, const float* __restrict__ aw_prev,
                       float* __restrict__ alpha_out){
    __shared__ float ws[32];
    __shared__ float redm[32];
    __shared__ float sh_max;
    int b = blockIdx.x, tid = threadIdx.x, lane = tid&31, wid = tid>>5;
    const float* em = g_em + b*TT;
    const float* ec = g_ec + b*TT;
    const float* nz = noise + b*TT;
    const float* aw = aw_prev + b*TT;
    float* ao = alpha_out + b*TT;
    float* seo = g_se + b*TT;

    float m = -3.4e38f;
    for (int t=tid; t<TT; t+=1024) m = fmaxf(m, ec[t]);
    #pragma unroll
    for (int o=16;o>0;o>>=1) m = fmaxf(m, __shfl_xor_sync(0xffffffffu, m, o));
    if (lane==0) redm[wid] = m;
    __syncthreads();
    if (wid==0){
        float mm = redm[lane];
        #pragma unroll
        for (int o=16;o>0;o>>=1) mm = fmaxf(mm, __shfl_xor_sync(0xffffffffu, mm, o));
        if (lane==0) sh_max = mm;
    }
    __syncthreads();
    float cmax = sh_max;

    float carry_l = 0.f, carry_r = 0.f;
    for (int tile=0; tile<TT/1024; tile++){
        int t = tile*1024 + tid;
        float e = em[t];
        float p = 1.f / (1.f + expf(-(e + nz[t])));
        float omp = fminf(fmaxf(1.f - p, EPSF), 1.f);
        float l = logf(omp);
        float Ls = blockScan(l, ws, tid);
        float total_l = ws[31];
        float cumprod = expf(carry_l + Ls - l);
        float cp_c = fminf(fmaxf(cumprod, EPSF), 1.f);
        float ratio = aw[t] / cp_c;
        float Rs = blockScan(ratio, ws, tid);
        float total_r = ws[31];
        float S2 = carry_r + Rs;
        ao[t] = p * cumprod * S2;
        seo[t] = fmaxf(expf(ec[t] - cmax), 1e-5f);
        carry_l += total_l;
        carry_r += total_r;
    }
}

// ---------------- beta ----------------
__global__ void k_beta(const float* __restrict__ alpha, float* __restrict__ beta){
    int b = blockIdx.y;
    int t = blockIdx.x*256 + threadIdx.x;
    const float* se = g_se + b*TT;
    float sum = 0.f;
    #pragma unroll
    for (int j=0;j<4;j++){
        int tj = t + j;
        if (tj < TT){
            float d = 0.f;
            #pragma unroll
            for (int i=0;i<4;i++){
                int ti = tj - i;
                if (ti >= 0) d += se[ti];
            }
            sum += alpha[b*TT + tj] / d;
        }
    }
    beta[b*TT + t] = se[t] * sum;
}

// ---------------- cv = beta . value ----------------
__global__ void k_initcv(float* out){
    int i = blockIdx.x*blockDim.x + threadIdx.x;
    if (i < BB*DD) out[i] = 0.f;
}

__global__ void k_cv(const float* __restrict__ value, const float* __restrict__ beta,
                     float* __restrict__ cv){
    int b = blockIdx.y;
    int s = blockIdx.x;
    int tid = threadIdx.x;
    int t0 = s * (TT/64);
    float4 acc = make_float4(0.f,0.f,0.f,0.f);
    const float4* val = (const float4*)(value + (size_t)b*TT*DD);
    for (int t=0; t<TT/64; t++){
        float bv = beta[b*TT + t0 + t];
        float4 v = val[(size_t)(t0+t)*(DD/4) + tid];
        acc.x += bv*v.x; acc.y += bv*v.y; acc.z += bv*v.z; acc.w += bv*v.w;
    }
    float* dst = cv + b*DD + tid*4;
    atomicAdd(dst+0, acc.x); atomicAdd(dst+1, acc.y);
    atomicAdd(dst+2, acc.z); atomicAdd(dst+3, acc.w);
}

// ---------------- launch ----------------
extern "C" void kernel_launch(void* const* d_in, const int* in_sizes, int n_in,
                              void* d_out, int out_size){
    const float* key   = (const float*)d_in[0];
    const float* value = (const float*)d_in[1];
    const float* query = (const float*)d_in[2];
    const float* noise = (const float*)d_in[3];
    const float* aw    = (const float*)d_in[4];
    // d_in[5] = mask, all-true by construction, ignored
    const float* m_wk = (const float*)d_in[6];
    const float* m_bk = (const float*)d_in[7];
    const float* m_wq = (const float*)d_in[8];
    const float* m_vv = (const float*)d_in[9];
    const float* m_vg = (const float*)d_in[10];
    const float* m_vb = (const float*)d_in[11];
    const float* m_r  = (const float*)d_in[12];
    const float* c_wk = (const float*)d_in[13];
    const float* c_bk = (const float*)d_in[14];
    const float* c_wq = (const float*)d_in[15];
    const float* c_vv = (const float*)d_in[16];
    const float* c_vg = (const float*)d_in[17];
    const float* c_vb = (const float*)d_in[18];
    const float* c_r  = (const float*)d_in[19];

    float* out   = (float*)d_out;
    float* cv    = out;                     // B*D
    float* alpha = out + BB*DD;             // B*T
    float* beta  = out + BB*DD + BB*TT;     // B*T

    cudaFuncSetAttribute(k_energy, cudaFuncAttributeMaxDynamicSharedMemorySize, SMEM_E);

    k_prep<<<1,512>>>(m_vv,m_vg,m_vb,m_r,c_vv,c_vg,c_vb,c_r);
    k_bias<<<dim3(BB,2),512>>>(query,m_wq,m_bk,c_wq,c_bk);
    k_convw<<<(DD*AA+255)/256,256>>>(m_wk,c_wk);
    k_energy<<<dim3(TT/64,BB),256,SMEM_E>>>(key);
    k_scan<<<BB,1024>>>(noise,aw,alpha);
    k_initcv<<<(BB*DD+1023)/1024,1024>>>(cv);
    k_beta<<<dim3(TT/256,BB),256>>>(alpha,beta);
    k_cv<<<dim3(64,BB),128>>>(value,beta,cv);
}

// round 14
// speedup vs baseline: 1.5589x; 1.0930x over previous
#include <cuda_runtime.h>
#include <cuda_bf16.h>
#include <math.h>
#include <cstdint>

#define BB 16
#define TT 8192
#define DD 512
#define AA 512
#define EPSF 1e-8f

// k_energy smem layout (per CTA, dynamic)
#define LDA_B 1040u        // A row stride bytes (520 bf16): 4-bank row shift, ldmatrix conflict-free
#define LDBW  144u         // B row stride bytes (64 n bf16 + 16B pad)
#define A_OFF 0u           // 64 rows x 1040B = 66560
#define BW_OFF 66560u      // 4 groups x 4 bufs x (16 rows x 144B) = 36864
#define BW_GRP 9216u       // per-group B bytes (4 buffers)
#define BW_BUF 2304u       // one buffer
#define BI_OFF 103424u     // 4 x 512 f32 = 8192
#define EB_OFF 111616u     // 64 f32
#define SMEM_E 111872u

__device__ __forceinline__ float tanh_fast(float x){
    float y; asm("tanh.approx.f32 %0, %1;" : "=f"(y) : "f"(x)); return y;
}
__device__ __forceinline__ uint32_t smem_u32(const void* p){
    uint32_t a;
    asm("{ .reg .u64 t; cvta.to.shared.u64 t, %1; cvt.u32.u64 %0, t; }" : "=r"(a) : "l"(p));
    return a;
}
__device__ __forceinline__ void cp_async16(uint32_t dst, const void* src){
    asm volatile("cp.async.cg.shared.global [%0], [%1], 16;" :: "r"(dst), "l"(src));
}
__device__ __forceinline__ void cp_commit(){ asm volatile("cp.async.commit_group;"); }
__device__ __forceinline__ void cp_wait2(){ asm volatile("cp.async.wait_group 2;"); }

__device__ __forceinline__ void ldmx4(uint32_t* r, uint32_t addr){
    asm volatile("ldmatrix.sync.aligned.m8n8.x4.shared.b16 {%0,%1,%2,%3}, [%4];"
        : "=r"(r[0]),"=r"(r[1]),"=r"(r[2]),"=r"(r[3]) : "r"(addr));
}
__device__ __forceinline__ void ldmx4t(uint32_t* r, uint32_t addr){
    asm volatile("ldmatrix.sync.aligned.m8n8.x4.trans.shared.b16 {%0,%1,%2,%3}, [%4];"
        : "=r"(r[0]),"=r"(r[1]),"=r"(r[2]),"=r"(r[3]) : "r"(addr));
}
__device__ __forceinline__ void mma16816(float* c, const uint32_t* a, const uint32_t* b){
    asm volatile("mma.sync.aligned.m16n8k16.row.col.f32.bf16.bf16.f32 "
        "{%0,%1,%2,%3}, {%4,%5,%6,%7}, {%8,%9}, {%0,%1,%2,%3};"
        : "+f"(c[0]),"+f"(c[1]),"+f"(c[2]),"+f"(c[3])
        : "r"(a[0]),"r"(a[1]),"r"(a[2]),"r"(a[3]), "r"(b[0]),"r"(b[1]));
}

// ---------------- device scratch ----------------
__device__ __align__(256) float g_bias_m[BB*AA];
__device__ __align__(256) float g_bias_c[BB*AA];
__device__ __align__(256) float g_wv[2*AA];
__device__ __align__(256) float g_add[2];
__device__ __align__(256) __nv_bfloat16 g_wkm[DD*AA];   // row-major [k][n]
__device__ __align__(256) __nv_bfloat16 g_wkc[DD*AA];
__device__ __align__(256) float g_em[BB*TT];
__device__ __align__(256) float g_ec[BB*TT];
__device__ __align__(256) float g_se[BB*TT];

// ---------------- prep: v_w scale + scalar biases ----------------
__global__ void k_prep(const float* __restrict__ m_vv, const float* __restrict__ m_vg,
                       const float* __restrict__ m_vb, const float* __restrict__ m_r,
                       const float* __restrict__ c_vv, const float* __restrict__ c_vg,
                       const float* __restrict__ c_vb, const float* __restrict__ c_r){
    __shared__ float red[512];
    int tid = threadIdx.x;
    float v = m_vv[tid];
    red[tid] = v*v;
    __syncthreads();
    for (int s=256; s>0; s>>=1){ if (tid<s) red[tid]+=red[tid+s]; __syncthreads(); }
    float scale_m = m_vg[0] / sqrtf(red[0]);
    __syncthreads();
    g_wv[tid] = v * scale_m;

    float vc = c_vv[tid];
    red[tid] = vc*vc;
    __syncthreads();
    for (int s=256; s>0; s>>=1){ if (tid<s) red[tid]+=red[tid+s]; __syncthreads(); }
    float scale_c = c_vg[0] / sqrtf(red[0]);
    g_wv[AA+tid] = vc * scale_c;
    if (tid==0){ g_add[0]=m_vb[0]+m_r[0]; g_add[1]=c_vb[0]+c_r[0]; }
}

// ---------------- bias: q@wq + bk ----------------
__global__ void k_bias(const float* __restrict__ query,
                       const float* __restrict__ m_wq, const float* __restrict__ m_bk,
                       const float* __restrict__ c_wq, const float* __restrict__ c_bk){
    __shared__ float q[DD];
    int b = blockIdx.x, which = blockIdx.y, tid = threadIdx.x;
    q[tid] = query[b*DD + tid];
    __syncthreads();
    const float* wq = which ? c_wq : m_wq;
    const float* bk = which ? c_bk : m_bk;
    float s = 0.f;
    #pragma unroll 8
    for (int d=0; d<DD; d++) s += q[d] * wq[d*AA + tid];
    float* dst = which ? g_bias_c : g_bias_m;
    dst[b*AA + tid] = s + bk[tid];
}

// ---------------- convert weights fp32 -> bf16 (row-major) ----------------
__global__ void k_convw(const float* __restrict__ m_wk, const float* __restrict__ c_wk){
    int i = blockIdx.x*blockDim.x + threadIdx.x;
    if (i < DD*AA){
        g_wkm[i] = __float2bfloat16(m_wk[i]);
        g_wkc[i] = __float2bfloat16(c_wk[i]);
    }
}

// ---------------- energy: PTX mma GEMM, M=64/CTA, 8 warps (2x4), tile 32x64 ----
// B pair-shared per warp_n group (4-deep buffers, cp.async by warp_m==0 only),
// 64-thread named-barrier handshake; NO block barrier in the k-loop.
// grid (TT/64, BB), 256 threads, 2 CTAs/SM = 4 warps/SMSP.
__global__ __launch_bounds__(256, 2)
void k_energy(const float* __restrict__ key){
    extern __shared__ char smem[];
    float* bias_s = (float*)(smem + BI_OFF);
    float* eb     = (float*)(smem + EB_OFF);
    uint32_t sb = smem_u32(smem);

    int tid = threadIdx.x, wid = tid >> 5, lane = tid & 31;
    int warp_m = wid >> 2, warp_n = wid & 3;     // 2 x 4 warp grid
    bool producer = (warp_m == 0);
    int barid = 1 + warp_n;
    int b = blockIdx.y, t0 = blockIdx.x * 64;

    // bias / wv into smem
    for (int i = tid; i < 512; i += 256){
        bias_s[i]        = g_bias_m[b*AA + i];
        bias_s[512 + i]  = g_bias_c[b*AA + i];
        bias_s[1024 + i] = g_wv[i];
        bias_s[1536 + i] = g_wv[AA + i];
    }

    // A fill: 64 rows x 512 fp32 -> bf16 smem (stride 1040B)
    {
        const float4* kv = (const float4*)(key + ((size_t)b*TT + t0)*DD);
        #pragma unroll 8
        for (int it = 0; it < 32; it++){
            int j = tid + 256*it;           // 0..8191
            int m = j >> 7;                 // row 0..63
            int c4 = j & 127;
            float4 v = kv[m*(DD/4) + c4];
            __nv_bfloat162 lo = __floats2bfloat162_rn(v.x, v.y);
            __nv_bfloat162 hi = __floats2bfloat162_rn(v.z, v.w);
            uint2 val = make_uint2(*(uint32_t*)&lo, *(uint32_t*)&hi);
            *(uint2*)(smem + A_OFF + (uint32_t)m*LDA_B + c4*8) = val;
        }
    }
    __syncthreads();

    // lane-level addresses
    uint32_t aBase = sb + A_OFF + (uint32_t)(warp_m*32 + (lane & 15))*LDA_B + (uint32_t)(lane >> 4)*16u;
    uint32_t grpBase = sb + BW_OFF + (uint32_t)warp_n*BW_GRP;
    uint32_t bLane   = grpBase + (uint32_t)(lane & 15)*LDBW + (uint32_t)(lane >> 4)*16u;
    int bRow = lane >> 3, bSeg = lane & 7;       // producer fill coords (4 iters of +4 rows)

    float acc[2][8][4];

    for (int pass = 0; pass < 2; pass++){
        const __nv_bfloat16* W = pass ? g_wkc : g_wkm;
        if (tid < 64) eb[tid] = 0.f;
        __syncthreads();

        for (int nt = 0; nt < 2; nt++){
            const char* Wbase = (const char*)W + (size_t)(nt*512 + warp_n*128);

            // prologue: producer fills buffers 0..2 (chunks 0..2); 3 commit groups
            if (producer){
                #pragma unroll
                for (int pf = 0; pf < 3; pf++){
                    const char* src = Wbase + (size_t)pf*16*(AA*2);
                    #pragma unroll
                    for (int i = 0; i < 4; i++){
                        int row = bRow + i*4;
                        cp_async16(grpBase + (uint32_t)pf*BW_BUF + (uint32_t)row*LDBW + bSeg*16,
                                   src + (size_t)row*(AA*2) + bSeg*16);
                    }
                    cp_commit();
                }
            }

            #pragma unroll
            for (int mi = 0; mi < 2; mi++)
                #pragma unroll
                for (int j = 0; j < 8; j++)
                    #pragma unroll
                    for (int c = 0; c < 4; c++) acc[mi][j][c] = 0.f;

            for (int kc = 0; kc < 32; kc++){
                // producer guarantees chunk kc landed; named bar publishes it to partner
                if (producer) cp_wait2();
                asm volatile("bar.sync %0, 64;" :: "r"(barid) : "memory");
                if (producer){
                    if (kc < 29){
                        const char* src = Wbase + (size_t)(kc+3)*16*(AA*2);
                        uint32_t dbuf = grpBase + (uint32_t)((kc+3)&3)*BW_BUF;
                        #pragma unroll
                        for (int i = 0; i < 4; i++){
                            int row = bRow + i*4;
                            cp_async16(dbuf + (uint32_t)row*LDBW + bSeg*16,
                                       src + (size_t)row*(AA*2) + bSeg*16);
                        }
                    }
                    cp_commit();   // empty at tail keeps group counting uniform
                }

                uint32_t aA = aBase + (uint32_t)kc*32u;       // 16 k = 32 bytes
                uint32_t bB = bLane + (uint32_t)(kc & 3)*BW_BUF;
                uint32_t a[2][4];
                ldmx4(a[0], aA);
                ldmx4(a[1], aA + 16u*LDA_B);
                uint32_t br[4][4];
                #pragma unroll
                for (int nq = 0; nq < 4; nq++)
                    ldmx4t(br[nq], bB + nq*32u);
                #pragma unroll
                for (int mi = 0; mi < 2; mi++)
                    #pragma unroll
                    for (int j = 0; j < 8; j++)
                        mma16816(acc[mi][j], a[mi], &br[j>>1][(j&1)*2]);
            }

            // direct-fragment epilogue: tanh(acc + bias) * wv over this warp's 64-n strip
            {
                const float2* bias2 = (const float2*)(bias_s + pass*512);
                const float2* wv2   = (const float2*)(bias_s + 1024 + pass*512);
                int cq = (nt*256 + warp_n*64 + (lane&3)*2) >> 1;   // float2 index
                #pragma unroll
                for (int mi = 0; mi < 2; mi++){
                    float slo = 0.f, shi = 0.f;
                    #pragma unroll
                    for (int j = 0; j < 8; j++){
                        float2 bw = bias2[cq + j*4];
                        float2 wv = wv2[cq + j*4];
                        slo += tanh_fast(acc[mi][j][0] + bw.x)*wv.x
                             + tanh_fast(acc[mi][j][1] + bw.y)*wv.y;
                        shi += tanh_fast(acc[mi][j][2] + bw.x)*wv.x
                             + tanh_fast(acc[mi][j][3] + bw.y)*wv.y;
                    }
                    slo += __shfl_xor_sync(0xffffffffu, slo, 1);
                    slo += __shfl_xor_sync(0xffffffffu, slo, 2);
                    shi += __shfl_xor_sync(0xffffffffu, shi, 1);
                    shi += __shfl_xor_sync(0xffffffffu, shi, 2);
                    if ((lane & 3) == 0){
                        int row = warp_m*32 + mi*16 + (lane >> 2);
                        atomicAdd(&eb[row],     slo);
                        atomicAdd(&eb[row + 8], shi);
                    }
                }
            }
        }
        __syncthreads();
        float* out = pass ? g_ec : g_em;
        if (tid < 64) out[b*TT + t0 + tid] = eb[tid] + g_add[pass];
        __syncthreads();
    }
}

// ---------------- block inclusive scan ----------------
__device__ __forceinline__ float blockScan(float v, float* ws, int tid){
    __syncthreads();
    int lane = tid & 31, wid = tid >> 5;
    float x = v;
    #pragma unroll
    for (int o=1;o<32;o<<=1){ float y=__shfl_up_sync(0xffffffffu, x, o); if (lane>=o) x+=y; }
    if (lane==31) ws[wid]=x;
    __syncthreads();
    if (wid==0){
        float w = ws[lane];
        #pragma unroll
        for (int o=1;o<32;o<<=1){ float y=__shfl_up_sync(0xffffffffu, w, o); if (lane>=o) w+=y; }
        ws[lane]=w;
    }
    __syncthreads();
    float off = wid ? ws[wid-1] : 0.f;
    return x + off;
}

__global__ void k_scan(const float* __restrict__ noise, const float* __restrict__ aw_prev,
                       float* __restrict__ alpha_out){
    __shared__ float ws[32];
    __shared__ float redm[32];
    __shared__ float sh_max;
    int b = blockIdx.x, tid = threadIdx.x, lane = tid&31, wid = tid>>5;
    const float* em = g_em + b*TT;
    const float* ec = g_ec + b*TT;
    const float* nz = noise + b*TT;
    const float* aw = aw_prev + b*TT;
    float* ao = alpha_out + b*TT;
    float* seo = g_se + b*TT;

    float m = -3.4e38f;
    for (int t=tid; t<TT; t+=1024) m = fmaxf(m, ec[t]);
    #pragma unroll
    for (int o=16;o>0;o>>=1) m = fmaxf(m, __shfl_xor_sync(0xffffffffu, m, o));
    if (lane==0) redm[wid] = m;
    __syncthreads();
    if (wid==0){
        float mm = redm[lane];
        #pragma unroll
        for (int o=16;o>0;o>>=1) mm = fmaxf(mm, __shfl_xor_sync(0xffffffffu, mm, o));
        if (lane==0) sh_max = mm;
    }
    __syncthreads();
    float cmax = sh_max;

    float carry_l = 0.f, carry_r = 0.f;
    for (int tile=0; tile<TT/1024; tile++){
        int t = tile*1024 + tid;
        float e = em[t];
        float p = 1.f / (1.f + expf(-(e + nz[t])));
        float omp = fminf(fmaxf(1.f - p, EPSF), 1.f);
        float l = logf(omp);
        float Ls = blockScan(l, ws, tid);
        float total_l = ws[31];
        float cumprod = expf(carry_l + Ls - l);
        float cp_c = fminf(fmaxf(cumprod, EPSF), 1.f);
        float ratio = aw[t] / cp_c;
        float Rs = blockScan(ratio, ws, tid);
        float total_r = ws[31];
        float S2 = carry_r + Rs;
        ao[t] = p * cumprod * S2;
        seo[t] = fmaxf(expf(ec[t] - cmax), 1e-5f);
        carry_l += total_l;
        carry_r += total_r;
    }
}

// ---------------- beta ----------------
__global__ void k_beta(const float* __restrict__ alpha, float* __restrict__ beta){
    int b = blockIdx.y;
    int t = blockIdx.x*256 + threadIdx.x;
    const float* se = g_se + b*TT;
    float sum = 0.f;
    #pragma unroll
    for (int j=0;j<4;j++){
        int tj = t + j;
        if (tj < TT){
            float d = 0.f;
            #pragma unroll
            for (int i=0;i<4;i++){
                int ti = tj - i;
                if (ti >= 0) d += se[ti];
            }
            sum += alpha[b*TT + tj] / d;
        }
    }
    beta[b*TT + t] = se[t] * sum;
}

// ---------------- cv = beta . value ----------------
__global__ void k_initcv(float* out){
    int i = blockIdx.x*blockDim.x + threadIdx.x;
    if (i < BB*DD) out[i] = 0.f;
}

__global__ void k_cv(const float* __restrict__ value, const float* __restrict__ beta,
                     float* __restrict__ cv){
    int b = blockIdx.y;
    int s = blockIdx.x;
    int tid = threadIdx.x;
    int t0 = s * (TT/64);
    float4 acc = make_float4(0.f,0.f,0.f,0.f);
    const float4* val = (const float4*)(value + (size_t)b*TT*DD);
    for (int t=0; t<TT/64; t++){
        float bv = beta[b*TT + t0 + t];
        float4 v = val[(size_t)(t0+t)*(DD/4) + tid];
        acc.x += bv*v.x; acc.y += bv*v.y; acc.z += bv*v.z; acc.w += bv*v.w;
    }
    float* dst = cv + b*DD + tid*4;
    atomicAdd(dst+0, acc.x); atomicAdd(dst+1, acc.y);
    atomicAdd(dst+2, acc.z); atomicAdd(dst+3, acc.w);
}

// ---------------- launch ----------------
extern "C" void kernel_launch(void* const* d_in, const int* in_sizes, int n_in,
                              void* d_out, int out_size){
    const float* key   = (const float*)d_in[0];
    const float* value = (const float*)d_in[1];
    const float* query = (const float*)d_in[2];
    const float* noise = (const float*)d_in[3];
    const float* aw    = (const float*)d_in[4];
    // d_in[5] = mask, all-true by construction, ignored
    const float* m_wk = (const float*)d_in[6];
    const float* m_bk = (const float*)d_in[7];
    const float* m_wq = (const float*)d_in[8];
    const float* m_vv = (const float*)d_in[9];
    const float* m_vg = (const float*)d_in[10];
    const float* m_vb = (const float*)d_in[11];
    const float* m_r  = (const float*)d_in[12];
    const float* c_wk = (const float*)d_in[13];
    const float* c_bk = (const float*)d_in[14];
    const float* c_wq = (const float*)d_in[15];
    const float* c_vv = (const float*)d_in[16];
    const float* c_vg = (const float*)d_in[17];
    const float* c_vb = (const float*)d_in[18];
    const float* c_r  = (const float*)d_in[19];

    float* out   = (float*)d_out;
    float* cv    = out;                     // B*D
    float* alpha = out + BB*DD;             // B*T
    float* beta  = out + BB*DD + BB*TT;     // B*T

    cudaFuncSetAttribute(k_energy, cudaFuncAttributeMaxDynamicSharedMemorySize, SMEM_E);

    k_prep<<<1,512>>>(m_vv,m_vg,m_vb,m_r,c_vv,c_vg,c_vb,c_r);
    k_bias<<<dim3(BB,2),512>>>(query,m_wq,m_bk,c_wq,c_bk);
    k_convw<<<(DD*AA+255)/256,256>>>(m_wk,c_wk);
    k_energy<<<dim3(TT/64,BB),256,SMEM_E>>>(key);
    k_scan<<<BB,1024>>>(noise,aw,alpha);
    k_initcv<<<(BB*DD+1023)/1024,1024>>>(cv);
    k_beta<<<dim3(TT/256,BB),256>>>(alpha,beta);
    k_cv<<<dim3(64,BB),128>>>(value,beta,cv);
}